// round 3
// baseline (speedup 1.0000x reference)
#include <cuda_runtime.h>
#include <cuda_bf16.h>

// CapsuleRoutingPooling collapses analytically:
// softmax over a size-1 axis == 1 -> routing loop is a no-op.
// out = squash( 2x2 sum-pool over spatial of the D=16 vectors ).
//
// Shapes: B=16, C=64, H=W=64, D=16, k=2 -> nH=nW=32,
// output vectors NVEC = 16*64*32*32 = 1,048,576.
//
// Persistent single-wave layout: 1024 blocks x 256 threads (all co-resident
// at regs~31, 8 blocks/SM on 148 SMs). 4 lanes per output vector; each
// 4-lane team processes 2 vectors per loop iteration (near half + far half,
// MLP=8), looping exactly 8 times -> zero wave-tail quantization.
// Loads: default caching. Stores: __stcs (output never re-read).

static constexpr int NVEC  = 16 * 64 * 32 * 32;   // 1,048,576
static constexpr int HALF  = NVEC / 2;            // 524,288
static constexpr int BLOCKS  = 1024;
static constexpr int THREADS = 256;
static constexpr int TEAMS   = BLOCKS * THREADS / 4;   // 65,536 teams
static constexpr int ITERS   = HALF / TEAMS;           // 8

__device__ __forceinline__ int vec_base4(int v, int lane) {
    int bc = v >> 10;          // b*C + c
    int t  = v & 1023;
    int nh = t >> 5;
    int nw = t & 31;
    // input row (b,c,h) = 256 float4s; w step = 4 float4s
    return (bc * 64 + (nh << 1)) * 256 + (nw << 3) + lane;
}

__device__ __forceinline__ float4 squash4(float4 s) {
    float sq = s.x * s.x + s.y * s.y + s.z * s.z + s.w * s.w;
    sq += __shfl_xor_sync(0xffffffffu, sq, 1);
    sq += __shfl_xor_sync(0xffffffffu, sq, 2);
    float scale = sq / ((1.0f + sq) * (sqrtf(sq) + 1e-8f));
    float4 o;
    o.x = s.x * scale; o.y = s.y * scale;
    o.z = s.z * scale; o.w = s.w * scale;
    return o;
}

__global__ void __launch_bounds__(THREADS)
capsule_pool_squash_kernel(const float* __restrict__ inp, float* __restrict__ out) {
    int gid  = blockIdx.x * THREADS + threadIdx.x;
    int team = gid >> 2;
    int lane = gid & 3;

    const float4* __restrict__ in4 = (const float4*)inp;
    float4* __restrict__ out4 = (float4*)out;

    #pragma unroll
    for (int it = 0; it < ITERS; ++it) {
        int v0 = team + it * TEAMS;     // first half of vector range
        int v1 = v0 + HALF;             // second half

        int base0 = vec_base4(v0, lane);
        int base1 = vec_base4(v1, lane);

        // 8 independent 16B loads in flight
        float4 a00 = in4[base0];
        float4 a01 = in4[base0 + 4];
        float4 a10 = in4[base0 + 256];
        float4 a11 = in4[base0 + 260];
        float4 b00 = in4[base1];
        float4 b01 = in4[base1 + 4];
        float4 b10 = in4[base1 + 256];
        float4 b11 = in4[base1 + 260];

        float4 sa, sb;
        sa.x = (a00.x + a01.x) + (a10.x + a11.x);
        sa.y = (a00.y + a01.y) + (a10.y + a11.y);
        sa.z = (a00.z + a01.z) + (a10.z + a11.z);
        sa.w = (a00.w + a01.w) + (a10.w + a11.w);
        sb.x = (b00.x + b01.x) + (b10.x + b11.x);
        sb.y = (b00.y + b01.y) + (b10.y + b11.y);
        sb.z = (b00.z + b01.z) + (b10.z + b11.z);
        sb.w = (b00.w + b01.w) + (b10.w + b11.w);

        float4 oa = squash4(sa);
        float4 ob = squash4(sb);

        __stcs(&out4[(v0 << 2) + lane], oa);
        __stcs(&out4[(v1 << 2) + lane], ob);
    }
}

extern "C" void kernel_launch(void* const* d_in, const int* in_sizes, int n_in,
                              void* d_out, int out_size) {
    const float* inp = (const float*)d_in[0];
    float* out = (float*)d_out;
    capsule_pool_squash_kernel<<<BLOCKS, THREADS>>>(inp, out);
}

// round 4
// speedup vs baseline: 1.1573x; 1.1573x over previous
#include <cuda_runtime.h>
#include <cuda_bf16.h>

// CapsuleRoutingPooling collapses analytically:
// softmax over a size-1 axis == 1 -> routing loop is a no-op.
// out = squash( 2x2 sum-pool over spatial of the D=16 vectors ).
//
// Shapes: B=16, C=64, H=W=64, D=16, k=2 -> nH=nW=32,
// output vectors = 16*64*32*32 = 1,048,576.
// 4 threads per output vector, one float4 each (Round-1 layout: best so far).
// Oversubscribed grid (16384 x 256) — persistent/single-wave variants regressed.
// Plain cached loads; __stcs streaming stores (output never re-read).

static constexpr int NVEC = 16 * 64 * 32 * 32;     // output vectors
static constexpr int NTHREADS_TOTAL = NVEC * 4;    // 4,194,304

__global__ void __launch_bounds__(256)
capsule_pool_squash_kernel(const float* __restrict__ inp, float* __restrict__ out) {
    int gid  = blockIdx.x * blockDim.x + threadIdx.x;
    int v    = gid >> 2;      // output vector id
    int lane = gid & 3;       // which float4 of the D=16 vector

    // v = ((bc)*32 + nh)*32 + nw
    int bc = v >> 10;         // b*C + c   (0..1023)
    int t  = v & 1023;
    int nh = t >> 5;
    int nw = t & 31;

    // input float4 indexing: row (b,c,h) has W*D/4 = 256 float4s; w step = D/4 = 4
    const float4* __restrict__ in4 = (const float4*)inp;
    int base4 = (bc * 64 + (nh << 1)) * 256 + (nw << 3) + lane;

    float4 p00 = in4[base4];
    float4 p01 = in4[base4 + 4];
    float4 p10 = in4[base4 + 256];
    float4 p11 = in4[base4 + 260];

    float4 s;
    s.x = (p00.x + p01.x) + (p10.x + p11.x);
    s.y = (p00.y + p01.y) + (p10.y + p11.y);
    s.z = (p00.z + p01.z) + (p10.z + p11.z);
    s.w = (p00.w + p01.w) + (p10.w + p11.w);

    // squared norm over D=16: reduce across the 4 lanes of this vector
    float sq = s.x * s.x + s.y * s.y + s.z * s.z + s.w * s.w;
    sq += __shfl_xor_sync(0xffffffffu, sq, 1);
    sq += __shfl_xor_sync(0xffffffffu, sq, 2);

    // squash scale: sq/(1+sq) * 1/(sqrt(sq)+1e-8)
    float scale = sq / ((1.0f + sq) * (sqrtf(sq) + 1e-8f));

    float4 o;
    o.x = s.x * scale;
    o.y = s.y * scale;
    o.z = s.z * scale;
    o.w = s.w * scale;

    __stcs(&((float4*)out)[(v << 2) + lane], o);
}

extern "C" void kernel_launch(void* const* d_in, const int* in_sizes, int n_in,
                              void* d_out, int out_size) {
    const float* inp = (const float*)d_in[0];
    float* out = (float*)d_out;
    int threads = 256;
    int blocks = NTHREADS_TOTAL / threads;   // 16384
    capsule_pool_squash_kernel<<<blocks, threads>>>(inp, out);
}